// round 3
// baseline (speedup 1.0000x reference)
#include <cuda_runtime.h>
#include <cstdint>

#define NN 100000
#define EE 1200000

// ---------------- device scratch (static, allocation-free) ----------------
__device__ int   g_cnt[2 * NN];
__device__ int   g_rp_pos[NN + 1];
__device__ int   g_rp_neg[NN + 1];
__device__ int   g_cur_pos[NN];
__device__ int   g_cur_neg[NN];
__device__ float g_inv_pos[NN];
__device__ float g_inv_neg[NN];
__device__ int   g_src_pos[EE];
__device__ int   g_src_neg[EE];
__device__ int   g_bsum[128];
__device__ float g_U0[NN * 256];    // [yp(64) | yn(64) | sp(64) | sn(64)]
__device__ float g_Z[NN * 128];     // z after layer 0
__device__ float g_Z2[NN * 128];    // z after layer 1
__device__ float g_AGGP[NN * 128];  // [Apos[0:64] | Aneg[64:128]]  (p-half inputs)
__device__ float g_AGGN[NN * 128];  // [Apos[64:128] | Aneg[0:64]]  (n-half inputs)

// ---------------- f32x2 packed-FMA helpers ----------------
__device__ __forceinline__ unsigned long long pack_dup(float x) {
    unsigned long long r;
    asm("mov.b64 %0, {%1, %1};" : "=l"(r) : "f"(x));
    return r;
}
__device__ __forceinline__ void ffma2(unsigned long long& d, unsigned long long a, unsigned long long b) {
    asm("fma.rn.f32x2 %0, %1, %2, %0;" : "+l"(d) : "l"(a), "l"(b));
}
__device__ __forceinline__ float2 unpack2(unsigned long long v) {
    float2 r;
    asm("mov.b64 {%0, %1}, %2;" : "=f"(r.x), "=f"(r.y) : "l"(v));
    return r;
}

// ---------------- CSR build ----------------
__global__ void zero_cnt_k() {
    int i = blockIdx.x * blockDim.x + threadIdx.x;
    if (i < 2 * NN) g_cnt[i] = 0;
}

__global__ void hist_k(const int* __restrict__ dst, int which) {
    int* cnt = g_cnt + which * NN;
    for (int i = blockIdx.x * blockDim.x + threadIdx.x; i < EE; i += gridDim.x * blockDim.x)
        atomicAdd(&cnt[dst[i]], 1);
}

__global__ void scan1_k(int which) {
    const int* cnt = g_cnt + which * NN;
    int* incl = which ? g_rp_neg : g_rp_pos;
    __shared__ int sh[1024];
    int i = blockIdx.x * 1024 + threadIdx.x;
    int v = (i < NN) ? cnt[i] : 0;
    sh[threadIdx.x] = v;
    __syncthreads();
    for (int off = 1; off < 1024; off <<= 1) {
        int t = (threadIdx.x >= off) ? sh[threadIdx.x - off] : 0;
        __syncthreads();
        sh[threadIdx.x] += t;
        __syncthreads();
    }
    if (i < NN) incl[i] = sh[threadIdx.x];
    if (threadIdx.x == 1023) g_bsum[blockIdx.x] = sh[1023];
}

__global__ void scan2_k(int nb) {
    __shared__ int sh[128];
    int v = (threadIdx.x < nb) ? g_bsum[threadIdx.x] : 0;
    sh[threadIdx.x] = v;
    __syncthreads();
    for (int off = 1; off < 128; off <<= 1) {
        int t = (threadIdx.x >= off) ? sh[threadIdx.x - off] : 0;
        __syncthreads();
        sh[threadIdx.x] += t;
        __syncthreads();
    }
    if (threadIdx.x < nb) g_bsum[threadIdx.x] = sh[threadIdx.x] - v;  // exclusive
}

__global__ void scan3_k(int which) {
    const int* cnt = g_cnt + which * NN;
    int* rp = which ? g_rp_neg : g_rp_pos;
    int* cur = which ? g_cur_neg : g_cur_pos;
    float* inv = which ? g_inv_neg : g_inv_pos;
    int i = blockIdx.x * blockDim.x + threadIdx.x;
    if (i < NN) {
        int inc = rp[i] + g_bsum[i >> 10];
        int c = cnt[i];
        int ex = inc - c;
        rp[i] = ex;
        cur[i] = ex;
        inv[i] = 1.0f / (float)(c > 0 ? c : 1);
    }
    if (i == 0) rp[NN] = EE;
}

__global__ void scatter_k(const int* __restrict__ src, const int* __restrict__ dst, int which) {
    int* cur = which ? g_cur_neg : g_cur_pos;
    int* out = which ? g_src_neg : g_src_pos;
    for (int i = blockIdx.x * blockDim.x + threadIdx.x; i < EE; i += gridDim.x * blockDim.x) {
        int d = dst[i];
        int p = atomicAdd(&cur[d], 1);
        out[p] = src[i];
    }
}

// ---------------- GEMM0: U0 col-block = x @ W  (K=128 -> 64 cols) ----------------
__global__ void __launch_bounds__(256) gemm0_k(const float* __restrict__ X, const float* __restrict__ W, int colOff) {
    __shared__ __align__(16) float sW[64 * 64];
    __shared__ __align__(16) float sIn[64 * 68];
    int tid = threadIdx.x;
    int v0 = blockIdx.x * 64;
    int nEnd = NN - v0; if (nEnd > 64) nEnd = 64;
    int c = tid & 15, g = tid >> 4;
    unsigned long long acc[4][2] = {};

    for (int kc = 0; kc < 2; kc++) {
        for (int idx = tid; idx < 64 * 16; idx += 256) {
            int k = idx >> 4, q = idx & 15;
            *(float4*)(sW + k * 64 + q * 4) = *(const float4*)(W + (kc * 64 + k) * 64 + q * 4);
        }
        for (int idx = tid; idx < 64 * 16; idx += 256) {
            int n = idx >> 4, q = idx & 15;
            float4 t = make_float4(0.f, 0.f, 0.f, 0.f);
            if (n < nEnd) t = *(const float4*)(X + (v0 + n) * 128 + kc * 64 + q * 4);
            int k = q * 4;
            sIn[(k + 0) * 68 + n] = t.x;
            sIn[(k + 1) * 68 + n] = t.y;
            sIn[(k + 2) * 68 + n] = t.z;
            sIn[(k + 3) * 68 + n] = t.w;
        }
        __syncthreads();
        const float* wp = sW + c * 4;
        const float* ip = sIn + g * 4;
#pragma unroll 8
        for (int k = 0; k < 64; k++) {
            ulonglong2 w = *(const ulonglong2*)(wp + k * 64);
            float4 a = *(const float4*)(ip + k * 68);
            unsigned long long a0 = pack_dup(a.x), a1 = pack_dup(a.y);
            unsigned long long a2 = pack_dup(a.z), a3 = pack_dup(a.w);
            ffma2(acc[0][0], a0, w.x); ffma2(acc[0][1], a0, w.y);
            ffma2(acc[1][0], a1, w.x); ffma2(acc[1][1], a1, w.y);
            ffma2(acc[2][0], a2, w.x); ffma2(acc[2][1], a2, w.y);
            ffma2(acc[3][0], a3, w.x); ffma2(acc[3][1], a3, w.y);
        }
        __syncthreads();
    }
#pragma unroll
    for (int nn = 0; nn < 4; nn++) {
        int n = g * 4 + nn;
        if (n < nEnd) {
            float2 lo = unpack2(acc[nn][0]), hi = unpack2(acc[nn][1]);
            *(float4*)(g_U0 + (v0 + n) * 256 + colOff + c * 4) = make_float4(lo.x, lo.y, hi.x, hi.y);
        }
    }
}

// ---------------- Layer 0: warp-per-node mean-gather + self + bias + tanh ----------------
__global__ void layer0_k(const float* __restrict__ bp, const float* __restrict__ bn) {
    int v = (blockIdx.x * blockDim.x + threadIdx.x) >> 5;
    int lane = threadIdx.x & 31;
    if (v >= NN) return;
    int c2 = lane * 2;
    float ax = 0.f, ay = 0.f, nx = 0.f, ny = 0.f;
    int b = g_rp_pos[v], e = g_rp_pos[v + 1];
    for (int i = b; i < e; i++) {
        int s = g_src_pos[i];
        float2 t = *(const float2*)(g_U0 + s * 256 + c2);
        ax += t.x; ay += t.y;
    }
    b = g_rp_neg[v]; e = g_rp_neg[v + 1];
    for (int i = b; i < e; i++) {
        int s = g_src_neg[i];
        float2 t = *(const float2*)(g_U0 + s * 256 + 64 + c2);
        nx += t.x; ny += t.y;
    }
    float ipv = g_inv_pos[v], inv = g_inv_neg[v];
    float2 sp = *(const float2*)(g_U0 + v * 256 + 128 + c2);
    float2 sn = *(const float2*)(g_U0 + v * 256 + 192 + c2);
    float2 b1 = *(const float2*)(bp + c2);
    float2 b2 = *(const float2*)(bn + c2);
    float2 zp = make_float2(tanhf(ax * ipv + sp.x + b1.x), tanhf(ay * ipv + sp.y + b1.y));
    float2 zn = make_float2(tanhf(nx * inv + sn.x + b2.x), tanhf(ny * inv + sn.y + b2.y));
    *(float2*)(g_Z + v * 128 + c2) = zp;
    *(float2*)(g_Z + v * 128 + 64 + c2) = zn;
}

// ---------------- Layer aggregation: warp-per-node, both edge sets, permuted output ----------------
__global__ void agg_k(int zsel) {
    const float* Z = zsel ? g_Z2 : g_Z;
    int v = (blockIdx.x * blockDim.x + threadIdx.x) >> 5;
    int lane = threadIdx.x & 31;
    if (v >= NN) return;
    int c4 = lane * 4;
    float4 aP = make_float4(0.f, 0.f, 0.f, 0.f);
    float4 aN = make_float4(0.f, 0.f, 0.f, 0.f);
    int b = g_rp_pos[v], e = g_rp_pos[v + 1];
    for (int i = b; i < e; i++) {
        int s = g_src_pos[i];
        float4 t = *(const float4*)(Z + s * 128 + c4);
        aP.x += t.x; aP.y += t.y; aP.z += t.z; aP.w += t.w;
    }
    b = g_rp_neg[v]; e = g_rp_neg[v + 1];
    for (int i = b; i < e; i++) {
        int s = g_src_neg[i];
        float4 t = *(const float4*)(Z + s * 128 + c4);
        aN.x += t.x; aN.y += t.y; aN.z += t.z; aN.w += t.w;
    }
    float ipv = g_inv_pos[v], inv = g_inv_neg[v];
    aP.x *= ipv; aP.y *= ipv; aP.z *= ipv; aP.w *= ipv;
    aN.x *= inv; aN.y *= inv; aN.z *= inv; aN.w *= inv;
    if (lane < 16) {
        *(float4*)(g_AGGP + v * 128 + c4) = aP;          // Apos[0:64]
        *(float4*)(g_AGGN + v * 128 + 64 + c4) = aN;     // Aneg[0:64] -> AGGN[64:128]
    } else {
        *(float4*)(g_AGGP + v * 128 + c4) = aN;          // Aneg[64:128]
        *(float4*)(g_AGGN + v * 128 + c4 - 64) = aP;     // Apos[64:128] -> AGGN[0:64]
    }
}

// ---------------- Layer GEMM (one half): out = tanh([AGGh | z_half] @ [Wl;Wr] + b) ----------------
__global__ void __launch_bounds__(256) layer_gemm_k(int half, int zsel,
                                                    const float* __restrict__ Wl,
                                                    const float* __restrict__ Wr,
                                                    const float* __restrict__ bias,
                                                    float* __restrict__ outExt) {
    __shared__ __align__(16) float sW[64 * 64];
    __shared__ __align__(16) float sIn[64 * 68];
    const float* AGGh = half ? g_AGGN : g_AGGP;
    const float* Zin = zsel ? g_Z2 : g_Z;
    float* out = outExt ? outExt : g_Z2;
    int zOff = half * 64, outOff = half * 64;

    int tid = threadIdx.x;
    int v0 = blockIdx.x * 64;
    int nEnd = NN - v0; if (nEnd > 64) nEnd = 64;
    int c = tid & 15, g = tid >> 4;
    unsigned long long acc[4][2] = {};

    for (int kc = 0; kc < 3; kc++) {
        for (int idx = tid; idx < 64 * 16; idx += 256) {
            int k = idx >> 4, q = idx & 15;
            int kg = kc * 64 + k;
            float4 w = (kg < 128) ? *(const float4*)(Wl + kg * 64 + q * 4)
                                  : *(const float4*)(Wr + (kg - 128) * 64 + q * 4);
            *(float4*)(sW + k * 64 + q * 4) = w;
        }
        for (int idx = tid; idx < 64 * 16; idx += 256) {
            int n = idx >> 4, q = idx & 15;
            float4 t = make_float4(0.f, 0.f, 0.f, 0.f);
            if (n < nEnd) {
                if (kc < 2) t = *(const float4*)(AGGh + (v0 + n) * 128 + kc * 64 + q * 4);
                else        t = *(const float4*)(Zin + (v0 + n) * 128 + zOff + q * 4);
            }
            int k = q * 4;
            sIn[(k + 0) * 68 + n] = t.x;
            sIn[(k + 1) * 68 + n] = t.y;
            sIn[(k + 2) * 68 + n] = t.z;
            sIn[(k + 3) * 68 + n] = t.w;
        }
        __syncthreads();
        const float* wp = sW + c * 4;
        const float* ip = sIn + g * 4;
#pragma unroll 8
        for (int k = 0; k < 64; k++) {
            ulonglong2 w = *(const ulonglong2*)(wp + k * 64);
            float4 a = *(const float4*)(ip + k * 68);
            unsigned long long a0 = pack_dup(a.x), a1 = pack_dup(a.y);
            unsigned long long a2 = pack_dup(a.z), a3 = pack_dup(a.w);
            ffma2(acc[0][0], a0, w.x); ffma2(acc[0][1], a0, w.y);
            ffma2(acc[1][0], a1, w.x); ffma2(acc[1][1], a1, w.y);
            ffma2(acc[2][0], a2, w.x); ffma2(acc[2][1], a2, w.y);
            ffma2(acc[3][0], a3, w.x); ffma2(acc[3][1], a3, w.y);
        }
        __syncthreads();
    }
    float4 bv = *(const float4*)(bias + c * 4);
#pragma unroll
    for (int nn = 0; nn < 4; nn++) {
        int n = g * 4 + nn;
        if (n < nEnd) {
            float2 lo = unpack2(acc[nn][0]), hi = unpack2(acc[nn][1]);
            float4 o = make_float4(tanhf(lo.x + bv.x), tanhf(lo.y + bv.y),
                                   tanhf(hi.x + bv.z), tanhf(hi.y + bv.w));
            *(float4*)(out + (v0 + n) * 128 + outOff + c * 4) = o;
        }
    }
}

// ---------------- host launcher ----------------
extern "C" void kernel_launch(void* const* d_in, const int* in_sizes, int n_in,
                              void* d_out, int out_size) {
    const float* x = (const float*)d_in[0];
    const int* pe = (const int*)d_in[1];   // int32! (JAX x64 disabled)
    const int* ne = (const int*)d_in[2];
    const float* Wp_l = (const float*)d_in[3];
    const float* Wp_r = (const float*)d_in[4];
    const float* bp = (const float*)d_in[5];
    const float* Wn_l = (const float*)d_in[6];
    const float* Wn_r = (const float*)d_in[7];
    const float* bn = (const float*)d_in[8];
    const float* Wl_pos = (const float*)d_in[9];
    const float* Wr_pos = (const float*)d_in[10];
    const float* b_pos = (const float*)d_in[11];
    const float* Wl_neg = (const float*)d_in[12];
    const float* Wr_neg = (const float*)d_in[13];
    const float* b_neg = (const float*)d_in[14];
    float* out = (float*)d_out;

    // --- CSR build for both edge sets ---
    zero_cnt_k<<<(2 * NN + 255) / 256, 256>>>();
    hist_k<<<1024, 256>>>(pe + EE, 0);
    hist_k<<<1024, 256>>>(ne + EE, 1);
    const int NB = (NN + 1023) / 1024;  // 98
    scan1_k<<<NB, 1024>>>(0);
    scan2_k<<<1, 128>>>(NB);
    scan3_k<<<(NN + 255) / 256, 256>>>(0);
    scatter_k<<<1024, 256>>>(pe, pe + EE, 0);
    scan1_k<<<NB, 1024>>>(1);
    scan2_k<<<1, 128>>>(NB);
    scan3_k<<<(NN + 255) / 256, 256>>>(1);
    scatter_k<<<1024, 256>>>(ne, ne + EE, 1);

    // --- layer 0: pre-GEMM x into [yp|yn|sp|sn], then gather 64-feat means ---
    const int NBG = (NN + 63) / 64;  // 1563
    gemm0_k<<<NBG, 256>>>(x, Wp_l, 0);
    gemm0_k<<<NBG, 256>>>(x, Wn_l, 64);
    gemm0_k<<<NBG, 256>>>(x, Wp_r, 128);
    gemm0_k<<<NBG, 256>>>(x, Wn_r, 192);
    const int NBW = (NN * 32 + 255) / 256;  // warp per node
    layer0_k<<<NBW, 256>>>(bp, bn);

    // --- layer 1: agg(z in g_Z) -> gemm -> g_Z2 ---
    agg_k<<<NBW, 256>>>(0);
    layer_gemm_k<<<NBG, 256>>>(0, 0, Wl_pos, Wr_pos, b_pos, nullptr);
    layer_gemm_k<<<NBG, 256>>>(1, 0, Wl_neg, Wr_neg, b_neg, nullptr);

    // --- layer 2: agg(z in g_Z2) -> gemm -> d_out ---
    agg_k<<<NBW, 256>>>(1);
    layer_gemm_k<<<NBG, 256>>>(0, 1, Wl_pos + 128 * 64, Wr_pos + 64 * 64, b_pos + 64, out);
    layer_gemm_k<<<NBG, 256>>>(1, 1, Wl_neg + 128 * 64, Wr_neg + 64 * 64, b_neg + 64, out);
}

// round 6
// speedup vs baseline: 1.3316x; 1.3316x over previous
#include <cuda_runtime.h>
#include <cstdint>

#define NN 100000
#define EE 1200000

// ---------------- device scratch (static, allocation-free) ----------------
__device__ int   g_cnt[2 * NN];
__device__ int   g_rp_pos[NN + 1];
__device__ int   g_rp_neg[NN + 1];
__device__ int   g_cur_pos[NN];
__device__ int   g_cur_neg[NN];
__device__ float g_inv_pos[NN];
__device__ float g_inv_neg[NN];
__device__ int   g_src_pos[EE];
__device__ int   g_src_neg[EE];
__device__ int   g_bsum[128];
__device__ float g_U0[NN * 256];    // [yp(64) | yn(64) | sp(64) | sn(64)]
__device__ float g_Z[NN * 128];     // z after layer 0
__device__ float g_Z2[NN * 128];    // z after layer 1
__device__ float g_AGGP[NN * 128];  // [Apos[0:64] | Aneg[64:128]]
__device__ float g_AGGN[NN * 128];  // [Apos[64:128] | Aneg[0:64]]

// packed bf16 weights: 4 layer stacks (24576 B each) then gemm0 (2 x 32768 B) = 163840 B
__device__ __align__(16) uint32_t g_WB_h[40960];
__device__ __align__(16) uint32_t g_WB_l[40960];

// ---------------- helpers ----------------
__device__ __forceinline__ uint32_t smem_u32(const void* p) {
    uint32_t a;
    asm("{ .reg .u64 t; cvta.to.shared.u64 t, %1; cvt.u32.u64 %0, t; }" : "=r"(a) : "l"(p));
    return a;
}
__device__ __forceinline__ uint32_t swz(uint32_t o) { return o ^ ((o >> 3) & 0x70); }

__device__ __forceinline__ void split_pair(float2 v, uint32_t& h2, uint32_t& l2) {
    asm("cvt.rn.bf16x2.f32 %0, %1, %2;" : "=r"(h2) : "f"(v.y), "f"(v.x));
    float lx = v.x - __uint_as_float(h2 << 16);
    float ly = v.y - __uint_as_float(h2 & 0xffff0000u);
    asm("cvt.rn.bf16x2.f32 %0, %1, %2;" : "=r"(l2) : "f"(ly), "f"(lx));
}

__device__ __forceinline__ void ldsm4(uint32_t* r, uint32_t addr) {
    asm volatile("ldmatrix.sync.aligned.m8n8.x4.shared.b16 {%0,%1,%2,%3}, [%4];"
                 : "=r"(r[0]), "=r"(r[1]), "=r"(r[2]), "=r"(r[3]) : "r"(addr));
}

__device__ __forceinline__ void mma16816(float* c, const uint32_t* a, const uint32_t* b) {
    asm volatile(
        "mma.sync.aligned.m16n8k16.row.col.f32.bf16.bf16.f32 "
        "{%0,%1,%2,%3}, {%4,%5,%6,%7}, {%8,%9}, {%0,%1,%2,%3};"
        : "+f"(c[0]), "+f"(c[1]), "+f"(c[2]), "+f"(c[3])
        : "r"(a[0]), "r"(a[1]), "r"(a[2]), "r"(a[3]), "r"(b[0]), "r"(b[1]));
}

// ---------------- CSR build (unchanged, passing) ----------------
__global__ void zero_cnt_k() {
    int i = blockIdx.x * blockDim.x + threadIdx.x;
    if (i < 2 * NN) g_cnt[i] = 0;
}
__global__ void hist_k(const int* __restrict__ dst, int which) {
    int* cnt = g_cnt + which * NN;
    for (int i = blockIdx.x * blockDim.x + threadIdx.x; i < EE; i += gridDim.x * blockDim.x)
        atomicAdd(&cnt[dst[i]], 1);
}
__global__ void scan1_k(int which) {
    const int* cnt = g_cnt + which * NN;
    int* incl = which ? g_rp_neg : g_rp_pos;
    __shared__ int sh[1024];
    int i = blockIdx.x * 1024 + threadIdx.x;
    int v = (i < NN) ? cnt[i] : 0;
    sh[threadIdx.x] = v;
    __syncthreads();
    for (int off = 1; off < 1024; off <<= 1) {
        int t = (threadIdx.x >= off) ? sh[threadIdx.x - off] : 0;
        __syncthreads();
        sh[threadIdx.x] += t;
        __syncthreads();
    }
    if (i < NN) incl[i] = sh[threadIdx.x];
    if (threadIdx.x == 1023) g_bsum[blockIdx.x] = sh[1023];
}
__global__ void scan2_k(int nb) {
    __shared__ int sh[128];
    int v = (threadIdx.x < nb) ? g_bsum[threadIdx.x] : 0;
    sh[threadIdx.x] = v;
    __syncthreads();
    for (int off = 1; off < 128; off <<= 1) {
        int t = (threadIdx.x >= off) ? sh[threadIdx.x - off] : 0;
        __syncthreads();
        sh[threadIdx.x] += t;
        __syncthreads();
    }
    if (threadIdx.x < nb) g_bsum[threadIdx.x] = sh[threadIdx.x] - v;
}
__global__ void scan3_k(int which) {
    const int* cnt = g_cnt + which * NN;
    int* rp = which ? g_rp_neg : g_rp_pos;
    int* cur = which ? g_cur_neg : g_cur_pos;
    float* inv = which ? g_inv_neg : g_inv_pos;
    int i = blockIdx.x * blockDim.x + threadIdx.x;
    if (i < NN) {
        int inc = rp[i] + g_bsum[i >> 10];
        int c = cnt[i];
        int ex = inc - c;
        rp[i] = ex;
        cur[i] = ex;
        inv[i] = 1.0f / (float)(c > 0 ? c : 1);
    }
    if (i == 0) rp[NN] = EE;
}
__global__ void scatter_k(const int* __restrict__ src, const int* __restrict__ dst, int which) {
    int* cur = which ? g_cur_neg : g_cur_pos;
    int* out = which ? g_src_neg : g_src_pos;
    for (int i = blockIdx.x * blockDim.x + threadIdx.x; i < EE; i += gridDim.x * blockDim.x) {
        int d = dst[i];
        int p = atomicAdd(&cur[d], 1);
        out[p] = src[i];
    }
}

// ---------------- weight prep: fp32 -> bf16 hi/lo, [n][k] rows, SW128-swizzled 64-k chunks ----------------
__global__ void prep_w_k(const float* __restrict__ Wl_pos, const float* __restrict__ Wr_pos,
                         const float* __restrict__ Wl_neg, const float* __restrict__ Wr_neg,
                         const float* __restrict__ Wp_l, const float* __restrict__ Wn_l,
                         const float* __restrict__ Wp_r, const float* __restrict__ Wn_r) {
    int idx = blockIdx.x * blockDim.x + threadIdx.x;
    float2 v;
    uint32_t off;
    if (idx < 24576) {
        int stack = idx / 6144, rem = idx % 6144;
        int n = rem / 96, kp = rem % 96, k = kp * 2;
        int l = stack >> 1, h = stack & 1;
        const float* WL = h ? Wl_neg : Wl_pos;  // [2][128][64]
        const float* WR = h ? Wr_neg : Wr_pos;  // [2][64][64]
        if (k < 128) {
            v.x = WL[l * 8192 + k * 64 + n];
            v.y = WL[l * 8192 + (k + 1) * 64 + n];
        } else {
            int kk = k - 128;
            v.x = WR[l * 4096 + kk * 64 + n];
            v.y = WR[l * 4096 + (kk + 1) * 64 + n];
        }
        off = (uint32_t)stack * 24576u + (uint32_t)(k >> 6) * 8192u + swz((uint32_t)n * 128u + (k & 63) * 2u);
    } else if (idx < 24576 + 16384) {
        int j = idx - 24576;
        int colsel = j / 8192, rem = j % 8192;
        int n = rem / 64, kp = rem % 64, k = kp * 2;
        const float* W = (n < 64) ? (colsel ? Wp_r : Wp_l) : (colsel ? Wn_r : Wn_l);
        int nn = n & 63;
        v.x = W[k * 64 + nn];
        v.y = W[(k + 1) * 64 + nn];
        off = 98304u + (uint32_t)colsel * 32768u + (uint32_t)(k >> 6) * 16384u + swz((uint32_t)n * 128u + (k & 63) * 2u);
    } else {
        return;
    }
    uint32_t h2, l2;
    split_pair(v, h2, l2);
    g_WB_h[off >> 2] = h2;
    g_WB_l[off >> 2] = l2;
}

// ---------------- unified HMMA GEMM ----------------
// out[v][outOff + 0..63] = act( A[v] @ W + bias ), M-tile 128, N=64, K = nkc*64
// A rows: chunks 0,1 from A0 (128-float rows, k = kc*64+..), chunk 2 from A1 + zOff.
// W: pre-swizzled bf16 hi/lo chunks at g_WB_{h,l} byte offset bBase + kc*bStride.
// Split: C = Ah@Wh + Al@Wh + Ah@Wl.
__global__ void __launch_bounds__(256) mma_gemm_k(
    const float* __restrict__ A0, const float* __restrict__ A1, int zOff, int nkc,
    int bBase, int bStride,
    float* __restrict__ out, int oStride, int outOff,
    const float* __restrict__ bias, int act)
{
    __shared__ uint32_t sAh[4096], sAl[4096];   // 128 rows x 32 words (16 KB each)
    __shared__ uint32_t sBh[2048], sBl[2048];   // 64 rows x 32 words (8 KB each)
    int tid = threadIdx.x, wid = tid >> 5, lane = tid & 31;
    int v0 = blockIdx.x * 128;

    uint32_t aHb = smem_u32(sAh), aLb = smem_u32(sAl);
    uint32_t bHb = smem_u32(sBh), bLb = smem_u32(sBl);

    // per-thread ldmatrix address components
    int lr = lane & 7, g = lane >> 3;
    int arow = wid * 16 + lr + (g & 1) * 8;
    uint32_t aPreH = aHb + arow * 128, aPreL = aLb + arow * 128;
    uint32_t xmA = (uint32_t)(arow & 7) * 16;
    uint32_t kbA = (uint32_t)(g >> 1) * 16;
    int brow = lr + (g >> 1) * 8;          // n within 16-wide pair
    uint32_t xmB = (uint32_t)lr * 16;
    uint32_t kbB = (uint32_t)(g & 1) * 16;

    float acc[8][4] = {};

    for (int kc = 0; kc < nkc; kc++) {
        // stage B chunk (pre-swizzled copy)
        {
            const uint4* bh = (const uint4*)((const char*)g_WB_h + bBase + kc * bStride);
            const uint4* bl = (const uint4*)((const char*)g_WB_l + bBase + kc * bStride);
            for (int i = tid; i < 512; i += 256) {
                ((uint4*)sBh)[i] = bh[i];
                ((uint4*)sBl)[i] = bl[i];
            }
        }
        // stage A chunk: fp32 -> bf16 hi/lo, swizzled
        for (int idx = tid; idx < 4096; idx += 256) {
            int r = idx >> 5, kp = idx & 31;
            float2 v = make_float2(0.f, 0.f);
            if (v0 + r < NN) {
                const float* src = (kc == 2) ? (A1 + (size_t)(v0 + r) * 128 + zOff + kp * 2)
                                             : (A0 + (size_t)(v0 + r) * 128 + kc * 64 + kp * 2);
                v = *(const float2*)src;
            }
            uint32_t h2, l2;
            split_pair(v, h2, l2);
            uint32_t o = swz((uint32_t)r * 128u + (uint32_t)kp * 4u);
            *(uint32_t*)((char*)sAh + o) = h2;
            *(uint32_t*)((char*)sAl + o) = l2;
        }
        __syncthreads();

#pragma unroll
        for (int ks = 0; ks < 4; ks++) {
            uint32_t kb = ks * 32;
            uint32_t ah[4], al[4];
            ldsm4(ah, aPreH + ((kb + kbA) ^ xmA));
            ldsm4(al, aPreL + ((kb + kbA) ^ xmA));
#pragma unroll
            for (int nt2 = 0; nt2 < 4; nt2++) {
                int n = nt2 * 16 + brow;
                uint32_t bo = (uint32_t)n * 128 + ((kb + kbB) ^ xmB);
                uint32_t bh4[4], bl4[4];
                ldsm4(bh4, bHb + bo);
                ldsm4(bl4, bLb + bo);
                mma16816(acc[nt2 * 2],     ah, bh4);
                mma16816(acc[nt2 * 2 + 1], ah, bh4 + 2);
                mma16816(acc[nt2 * 2],     al, bh4);
                mma16816(acc[nt2 * 2 + 1], al, bh4 + 2);
                mma16816(acc[nt2 * 2],     ah, bl4);
                mma16816(acc[nt2 * 2 + 1], ah, bl4 + 2);
            }
        }
        __syncthreads();
    }

    // epilogue
    int r0 = v0 + wid * 16 + (lane >> 2);
    int cb = (lane & 3) * 2;
#pragma unroll
    for (int j = 0; j < 8; j++) {
        int col = j * 8 + cb;
        float bx = 0.f, by = 0.f;
        if (bias) { bx = bias[col]; by = bias[col + 1]; }
        float ox = acc[j][0] + bx, oy = acc[j][1] + by;
        float px = acc[j][2] + bx, py = acc[j][3] + by;
        if (act) { ox = tanhf(ox); oy = tanhf(oy); px = tanhf(px); py = tanhf(py); }
        if (r0 < NN)     *(float2*)(out + (size_t)r0 * oStride + outOff + col)       = make_float2(ox, oy);
        if (r0 + 8 < NN) *(float2*)(out + (size_t)(r0 + 8) * oStride + outOff + col) = make_float2(px, py);
    }
}

// ---------------- Layer 0: warp-per-node mean-gather + self + bias + tanh (unchanged) ----------------
__global__ void layer0_k(const float* __restrict__ bp, const float* __restrict__ bn) {
    int v = (blockIdx.x * blockDim.x + threadIdx.x) >> 5;
    int lane = threadIdx.x & 31;
    if (v >= NN) return;
    int c2 = lane * 2;
    float ax = 0.f, ay = 0.f, nx = 0.f, ny = 0.f;
    int b = g_rp_pos[v], e = g_rp_pos[v + 1];
    for (int i = b; i < e; i++) {
        int s = g_src_pos[i];
        float2 t = *(const float2*)(g_U0 + s * 256 + c2);
        ax += t.x; ay += t.y;
    }
    b = g_rp_neg[v]; e = g_rp_neg[v + 1];
    for (int i = b; i < e; i++) {
        int s = g_src_neg[i];
        float2 t = *(const float2*)(g_U0 + s * 256 + 64 + c2);
        nx += t.x; ny += t.y;
    }
    float ipv = g_inv_pos[v], inv = g_inv_neg[v];
    float2 sp = *(const float2*)(g_U0 + v * 256 + 128 + c2);
    float2 sn = *(const float2*)(g_U0 + v * 256 + 192 + c2);
    float2 b1 = *(const float2*)(bp + c2);
    float2 b2 = *(const float2*)(bn + c2);
    float2 zp = make_float2(tanhf(ax * ipv + sp.x + b1.x), tanhf(ay * ipv + sp.y + b1.y));
    float2 zn = make_float2(tanhf(nx * inv + sn.x + b2.x), tanhf(ny * inv + sn.y + b2.y));
    *(float2*)(g_Z + v * 128 + c2) = zp;
    *(float2*)(g_Z + v * 128 + 64 + c2) = zn;
}

// ---------------- Layer aggregation (unchanged) ----------------
__global__ void agg_k(int zsel) {
    const float* Z = zsel ? g_Z2 : g_Z;
    int v = (blockIdx.x * blockDim.x + threadIdx.x) >> 5;
    int lane = threadIdx.x & 31;
    if (v >= NN) return;
    int c4 = lane * 4;
    float4 aP = make_float4(0.f, 0.f, 0.f, 0.f);
    float4 aN = make_float4(0.f, 0.f, 0.f, 0.f);
    int b = g_rp_pos[v], e = g_rp_pos[v + 1];
    for (int i = b; i < e; i++) {
        int s = g_src_pos[i];
        float4 t = *(const float4*)(Z + s * 128 + c4);
        aP.x += t.x; aP.y += t.y; aP.z += t.z; aP.w += t.w;
    }
    b = g_rp_neg[v]; e = g_rp_neg[v + 1];
    for (int i = b; i < e; i++) {
        int s = g_src_neg[i];
        float4 t = *(const float4*)(Z + s * 128 + c4);
        aN.x += t.x; aN.y += t.y; aN.z += t.z; aN.w += t.w;
    }
    float ipv = g_inv_pos[v], inv = g_inv_neg[v];
    aP.x *= ipv; aP.y *= ipv; aP.z *= ipv; aP.w *= ipv;
    aN.x *= inv; aN.y *= inv; aN.z *= inv; aN.w *= inv;
    if (lane < 16) {
        *(float4*)(g_AGGP + v * 128 + c4) = aP;
        *(float4*)(g_AGGN + v * 128 + 64 + c4) = aN;
    } else {
        *(float4*)(g_AGGP + v * 128 + c4) = aN;
        *(float4*)(g_AGGN + v * 128 + c4 - 64) = aP;
    }
}

// ---------------- host launcher ----------------
extern "C" void kernel_launch(void* const* d_in, const int* in_sizes, int n_in,
                              void* d_out, int out_size) {
    const float* x = (const float*)d_in[0];
    const int* pe = (const int*)d_in[1];   // int32 (JAX x64 disabled)
    const int* ne = (const int*)d_in[2];
    const float* Wp_l = (const float*)d_in[3];
    const float* Wp_r = (const float*)d_in[4];
    const float* bp = (const float*)d_in[5];
    const float* Wn_l = (const float*)d_in[6];
    const float* Wn_r = (const float*)d_in[7];
    const float* bn = (const float*)d_in[8];
    const float* Wl_pos = (const float*)d_in[9];
    const float* Wr_pos = (const float*)d_in[10];
    const float* b_pos = (const float*)d_in[11];
    const float* Wl_neg = (const float*)d_in[12];
    const float* Wr_neg = (const float*)d_in[13];
    const float* b_neg = (const float*)d_in[14];
    float* out = (float*)d_out;

    // device-global symbol addresses (host side)
    float *dU0, *dZ, *dZ2, *dAGGP, *dAGGN;
    cudaGetSymbolAddress((void**)&dU0, g_U0);
    cudaGetSymbolAddress((void**)&dZ, g_Z);
    cudaGetSymbolAddress((void**)&dZ2, g_Z2);
    cudaGetSymbolAddress((void**)&dAGGP, g_AGGP);
    cudaGetSymbolAddress((void**)&dAGGN, g_AGGN);

    // --- weight prep (bf16 hi/lo packed tiles) ---
    prep_w_k<<<160, 256>>>(Wl_pos, Wr_pos, Wl_neg, Wr_neg, Wp_l, Wn_l, Wp_r, Wn_r);

    // --- CSR build ---
    zero_cnt_k<<<(2 * NN + 255) / 256, 256>>>();
    hist_k<<<1024, 256>>>(pe + EE, 0);
    hist_k<<<1024, 256>>>(ne + EE, 1);
    const int NB = (NN + 1023) / 1024;
    scan1_k<<<NB, 1024>>>(0);
    scan2_k<<<1, 128>>>(NB);
    scan3_k<<<(NN + 255) / 256, 256>>>(0);
    scatter_k<<<1024, 256>>>(pe, pe + EE, 0);
    scan1_k<<<NB, 1024>>>(1);
    scan2_k<<<1, 128>>>(NB);
    scan3_k<<<(NN + 255) / 256, 256>>>(1);
    scatter_k<<<1024, 256>>>(ne, ne + EE, 1);

    const int NBT = (NN + 127) / 128;  // 782

    // --- layer 0 pre-GEMMs: U0 = [x@Wp_l | x@Wn_l | x@Wp_r | x@Wn_r] ---
    // colsel c (0=left,1=right), half h (0=pos,1=neg): bBase = 98304 + c*32768 + h*8192
    for (int c = 0; c < 2; c++)
        for (int h = 0; h < 2; h++)
            mma_gemm_k<<<NBT, 256>>>(x, x, 0, 2,
                                     98304 + c * 32768 + h * 8192, 16384,
                                     dU0, 256, c * 128 + h * 64, nullptr, 0);
    const int NBW = (NN * 32 + 255) / 256;
    layer0_k<<<NBW, 256>>>(bp, bn);

    // --- layer 1 ---
    agg_k<<<NBW, 256>>>(0);
    mma_gemm_k<<<NBT, 256>>>(dAGGP, dZ, 0, 3, 0 * 24576, 8192, dZ2, 128, 0, b_pos, 1);
    mma_gemm_k<<<NBT, 256>>>(dAGGN, dZ, 64, 3, 1 * 24576, 8192, dZ2, 128, 64, b_neg, 1);

    // --- layer 2 ---
    agg_k<<<NBW, 256>>>(1);
    mma_gemm_k<<<NBT, 256>>>(dAGGP, dZ2, 0, 3, 2 * 24576, 8192, out, 128, 0, b_pos + 64, 1);
    mma_gemm_k<<<NBT, 256>>>(dAGGN, dZ2, 64, 3, 3 * 24576, 8192, out, 128, 64, b_neg + 64, 1);
}

// round 7
// speedup vs baseline: 1.4579x; 1.0948x over previous
#include <cuda_runtime.h>
#include <cuda_fp16.h>
#include <cstdint>

#define NN 100000
#define EE 1200000

// ---------------- device scratch (static, allocation-free) ----------------
__device__ int   g_cnt[2 * NN];
__device__ int   g_rp_pos[NN + 1];
__device__ int   g_rp_neg[NN + 1];
__device__ int   g_cur_pos[NN];
__device__ int   g_cur_neg[NN];
__device__ float g_inv_pos[NN];
__device__ float g_inv_neg[NN];
__device__ int   g_src_pos[EE];
__device__ int   g_src_neg[EE];
__device__ int   g_bsum[128];
__device__ __align__(16) __half g_U0h[NN * 128];  // [yp(64) | yn(64)] fp16 (gathered by layer0)
__device__ float g_U0s[NN * 128];                  // [sp(64) | sn(64)] fp32 (self terms)
__device__ __align__(16) __half g_Zh[NN * 128];   // z after layer 0 (fp16)
__device__ __align__(16) __half g_Z2h[NN * 128];  // z after layer 1 (fp16)
__device__ float g_AGGP[NN * 128];  // [Apos[0:64] | Aneg[64:128]]
__device__ float g_AGGN[NN * 128];  // [Apos[64:128] | Aneg[0:64]]

// packed bf16 weights: 4 layer stacks (24576 B each) then gemm0 (2 x 32768 B) = 163840 B
__device__ __align__(16) uint32_t g_WB_h[40960];
__device__ __align__(16) uint32_t g_WB_l[40960];

// ---------------- helpers ----------------
__device__ __forceinline__ uint32_t smem_u32(const void* p) {
    uint32_t a;
    asm("{ .reg .u64 t; cvta.to.shared.u64 t, %1; cvt.u32.u64 %0, t; }" : "=r"(a) : "l"(p));
    return a;
}
__device__ __forceinline__ uint32_t swz(uint32_t o) { return o ^ ((o >> 3) & 0x70); }

__device__ __forceinline__ void split_pair(float2 v, uint32_t& h2, uint32_t& l2) {
    asm("cvt.rn.bf16x2.f32 %0, %1, %2;" : "=r"(h2) : "f"(v.y), "f"(v.x));
    float lx = v.x - __uint_as_float(h2 << 16);
    float ly = v.y - __uint_as_float(h2 & 0xffff0000u);
    asm("cvt.rn.bf16x2.f32 %0, %1, %2;" : "=r"(l2) : "f"(ly), "f"(lx));
}

__device__ __forceinline__ void ldsm4(uint32_t* r, uint32_t addr) {
    asm volatile("ldmatrix.sync.aligned.m8n8.x4.shared.b16 {%0,%1,%2,%3}, [%4];"
                 : "=r"(r[0]), "=r"(r[1]), "=r"(r[2]), "=r"(r[3]) : "r"(addr));
}

__device__ __forceinline__ void mma16816(float* c, const uint32_t* a, const uint32_t* b) {
    asm volatile(
        "mma.sync.aligned.m16n8k16.row.col.f32.bf16.bf16.f32 "
        "{%0,%1,%2,%3}, {%4,%5,%6,%7}, {%8,%9}, {%0,%1,%2,%3};"
        : "+f"(c[0]), "+f"(c[1]), "+f"(c[2]), "+f"(c[3])
        : "r"(a[0]), "r"(a[1]), "r"(a[2]), "r"(a[3]), "r"(b[0]), "r"(b[1]));
}

// ---------------- CSR build (unchanged, passing) ----------------
__global__ void zero_cnt_k() {
    int i = blockIdx.x * blockDim.x + threadIdx.x;
    if (i < 2 * NN) g_cnt[i] = 0;
}
__global__ void hist_k(const int* __restrict__ dst, int which) {
    int* cnt = g_cnt + which * NN;
    for (int i = blockIdx.x * blockDim.x + threadIdx.x; i < EE; i += gridDim.x * blockDim.x)
        atomicAdd(&cnt[dst[i]], 1);
}
__global__ void scan1_k(int which) {
    const int* cnt = g_cnt + which * NN;
    int* incl = which ? g_rp_neg : g_rp_pos;
    __shared__ int sh[1024];
    int i = blockIdx.x * 1024 + threadIdx.x;
    int v = (i < NN) ? cnt[i] : 0;
    sh[threadIdx.x] = v;
    __syncthreads();
    for (int off = 1; off < 1024; off <<= 1) {
        int t = (threadIdx.x >= off) ? sh[threadIdx.x - off] : 0;
        __syncthreads();
        sh[threadIdx.x] += t;
        __syncthreads();
    }
    if (i < NN) incl[i] = sh[threadIdx.x];
    if (threadIdx.x == 1023) g_bsum[blockIdx.x] = sh[1023];
}
__global__ void scan2_k(int nb) {
    __shared__ int sh[128];
    int v = (threadIdx.x < nb) ? g_bsum[threadIdx.x] : 0;
    sh[threadIdx.x] = v;
    __syncthreads();
    for (int off = 1; off < 128; off <<= 1) {
        int t = (threadIdx.x >= off) ? sh[threadIdx.x - off] : 0;
        __syncthreads();
        sh[threadIdx.x] += t;
        __syncthreads();
    }
    if (threadIdx.x < nb) g_bsum[threadIdx.x] = sh[threadIdx.x] - v;
}
__global__ void scan3_k(int which) {
    const int* cnt = g_cnt + which * NN;
    int* rp = which ? g_rp_neg : g_rp_pos;
    int* cur = which ? g_cur_neg : g_cur_pos;
    float* inv = which ? g_inv_neg : g_inv_pos;
    int i = blockIdx.x * blockDim.x + threadIdx.x;
    if (i < NN) {
        int inc = rp[i] + g_bsum[i >> 10];
        int c = cnt[i];
        int ex = inc - c;
        rp[i] = ex;
        cur[i] = ex;
        inv[i] = 1.0f / (float)(c > 0 ? c : 1);
    }
    if (i == 0) rp[NN] = EE;
}
__global__ void scatter_k(const int* __restrict__ src, const int* __restrict__ dst, int which) {
    int* cur = which ? g_cur_neg : g_cur_pos;
    int* out = which ? g_src_neg : g_src_pos;
    for (int i = blockIdx.x * blockDim.x + threadIdx.x; i < EE; i += gridDim.x * blockDim.x) {
        int d = dst[i];
        int p = atomicAdd(&cur[d], 1);
        out[p] = src[i];
    }
}

// ---------------- weight prep: fp32 -> bf16 hi/lo, [n][k] rows, SW128-swizzled 64-k chunks ----------------
__global__ void prep_w_k(const float* __restrict__ Wl_pos, const float* __restrict__ Wr_pos,
                         const float* __restrict__ Wl_neg, const float* __restrict__ Wr_neg,
                         const float* __restrict__ Wp_l, const float* __restrict__ Wn_l,
                         const float* __restrict__ Wp_r, const float* __restrict__ Wn_r) {
    int idx = blockIdx.x * blockDim.x + threadIdx.x;
    float2 v;
    uint32_t off;
    if (idx < 24576) {
        int stack = idx / 6144, rem = idx % 6144;
        int n = rem / 96, kp = rem % 96, k = kp * 2;
        int l = stack >> 1, h = stack & 1;
        const float* WL = h ? Wl_neg : Wl_pos;  // [2][128][64]
        const float* WR = h ? Wr_neg : Wr_pos;  // [2][64][64]
        if (k < 128) {
            v.x = WL[l * 8192 + k * 64 + n];
            v.y = WL[l * 8192 + (k + 1) * 64 + n];
        } else {
            int kk = k - 128;
            v.x = WR[l * 4096 + kk * 64 + n];
            v.y = WR[l * 4096 + (kk + 1) * 64 + n];
        }
        off = (uint32_t)stack * 24576u + (uint32_t)(k >> 6) * 8192u + swz((uint32_t)n * 128u + (k & 63) * 2u);
    } else if (idx < 24576 + 16384) {
        int j = idx - 24576;
        int colsel = j / 8192, rem = j % 8192;
        int n = rem / 64, kp = rem % 64, k = kp * 2;
        const float* W = (n < 64) ? (colsel ? Wp_r : Wp_l) : (colsel ? Wn_r : Wn_l);
        int nn = n & 63;
        v.x = W[k * 64 + nn];
        v.y = W[(k + 1) * 64 + nn];
        off = 98304u + (uint32_t)colsel * 32768u + (uint32_t)(k >> 6) * 16384u + swz((uint32_t)n * 128u + (k & 63) * 2u);
    } else {
        return;
    }
    uint32_t h2, l2;
    split_pair(v, h2, l2);
    g_WB_h[off >> 2] = h2;
    g_WB_l[off >> 2] = l2;
}

// ---------------- unified HMMA GEMM ----------------
// A rows: chunks 0,1 (fp32) from A0; chunk 2 (fp16) from A1h + zOff.
// W: pre-swizzled bf16 hi/lo chunks. Split: C = Ah@Wh + Al@Wh + Ah@Wl.
// Output: fp32 (outF) or fp16 (outH) selected by outHalf.
__global__ void __launch_bounds__(256) mma_gemm_k(
    const float* __restrict__ A0, const __half* __restrict__ A1h, int zOff, int nkc,
    int bBase, int bStride,
    float* __restrict__ outF, __half* __restrict__ outH, int outOff,
    const float* __restrict__ bias, int act, int outHalf)
{
    __shared__ uint32_t sAh[4096], sAl[4096];   // 128 rows x 32 words (16 KB each)
    __shared__ uint32_t sBh[2048], sBl[2048];   // 64 rows x 32 words (8 KB each)
    int tid = threadIdx.x, wid = tid >> 5, lane = tid & 31;
    int v0 = blockIdx.x * 128;

    uint32_t aHb = smem_u32(sAh), aLb = smem_u32(sAl);
    uint32_t bHb = smem_u32(sBh), bLb = smem_u32(sBl);

    int lr = lane & 7, g = lane >> 3;
    int arow = wid * 16 + lr + (g & 1) * 8;
    uint32_t aPreH = aHb + arow * 128, aPreL = aLb + arow * 128;
    uint32_t xmA = (uint32_t)(arow & 7) * 16;
    uint32_t kbA = (uint32_t)(g >> 1) * 16;
    int brow = lr + (g >> 1) * 8;
    uint32_t xmB = (uint32_t)lr * 16;
    uint32_t kbB = (uint32_t)(g & 1) * 16;

    float acc[8][4] = {};

    for (int kc = 0; kc < nkc; kc++) {
        {
            const uint4* bh = (const uint4*)((const char*)g_WB_h + bBase + kc * bStride);
            const uint4* bl = (const uint4*)((const char*)g_WB_l + bBase + kc * bStride);
            for (int i = tid; i < 512; i += 256) {
                ((uint4*)sBh)[i] = bh[i];
                ((uint4*)sBl)[i] = bl[i];
            }
        }
        for (int idx = tid; idx < 4096; idx += 256) {
            int r = idx >> 5, kp = idx & 31;
            float2 v = make_float2(0.f, 0.f);
            if (v0 + r < NN) {
                if (kc == 2)
                    v = __half22float2(*(const __half2*)(A1h + (size_t)(v0 + r) * 128 + zOff + kp * 2));
                else
                    v = *(const float2*)(A0 + (size_t)(v0 + r) * 128 + kc * 64 + kp * 2);
            }
            uint32_t h2, l2;
            split_pair(v, h2, l2);
            uint32_t o = swz((uint32_t)r * 128u + (uint32_t)kp * 4u);
            *(uint32_t*)((char*)sAh + o) = h2;
            *(uint32_t*)((char*)sAl + o) = l2;
        }
        __syncthreads();

#pragma unroll
        for (int ks = 0; ks < 4; ks++) {
            uint32_t kb = ks * 32;
            uint32_t ah[4], al[4];
            ldsm4(ah, aPreH + ((kb + kbA) ^ xmA));
            ldsm4(al, aPreL + ((kb + kbA) ^ xmA));
#pragma unroll
            for (int nt2 = 0; nt2 < 4; nt2++) {
                int n = nt2 * 16 + brow;
                uint32_t bo = (uint32_t)n * 128 + ((kb + kbB) ^ xmB);
                uint32_t bh4[4], bl4[4];
                ldsm4(bh4, bHb + bo);
                ldsm4(bl4, bLb + bo);
                mma16816(acc[nt2 * 2],     ah, bh4);
                mma16816(acc[nt2 * 2 + 1], ah, bh4 + 2);
                mma16816(acc[nt2 * 2],     al, bh4);
                mma16816(acc[nt2 * 2 + 1], al, bh4 + 2);
                mma16816(acc[nt2 * 2],     ah, bl4);
                mma16816(acc[nt2 * 2 + 1], ah, bl4 + 2);
            }
        }
        __syncthreads();
    }

    // epilogue
    int r0 = v0 + wid * 16 + (lane >> 2);
    int cb = (lane & 3) * 2;
#pragma unroll
    for (int j = 0; j < 8; j++) {
        int col = j * 8 + cb;
        float bx = 0.f, by = 0.f;
        if (bias) { bx = bias[col]; by = bias[col + 1]; }
        float ox = acc[j][0] + bx, oy = acc[j][1] + by;
        float px = acc[j][2] + bx, py = acc[j][3] + by;
        if (act) { ox = tanhf(ox); oy = tanhf(oy); px = tanhf(px); py = tanhf(py); }
        if (outHalf) {
            if (r0 < NN)     *(__half2*)(outH + (size_t)r0 * 128 + outOff + col)       = __floats2half2_rn(ox, oy);
            if (r0 + 8 < NN) *(__half2*)(outH + (size_t)(r0 + 8) * 128 + outOff + col) = __floats2half2_rn(px, py);
        } else {
            if (r0 < NN)     *(float2*)(outF + (size_t)r0 * 128 + outOff + col)       = make_float2(ox, oy);
            if (r0 + 8 < NN) *(float2*)(outF + (size_t)(r0 + 8) * 128 + outOff + col) = make_float2(px, py);
        }
    }
}

// ---------------- Layer 0: warp-per-node fp16 mean-gather + self + bias + tanh ----------------
__global__ void layer0_k(const float* __restrict__ bp, const float* __restrict__ bn) {
    int v = (blockIdx.x * blockDim.x + threadIdx.x) >> 5;
    int lane = threadIdx.x & 31;
    if (v >= NN) return;
    int c2 = lane * 2;
    float ax = 0.f, ay = 0.f, nx = 0.f, ny = 0.f;
    int b = g_rp_pos[v], e = g_rp_pos[v + 1];
    for (int i = b; i < e; i++) {
        int s = g_src_pos[i];
        float2 t = __half22float2(*(const __half2*)(g_U0h + (size_t)s * 128 + c2));
        ax += t.x; ay += t.y;
    }
    b = g_rp_neg[v]; e = g_rp_neg[v + 1];
    for (int i = b; i < e; i++) {
        int s = g_src_neg[i];
        float2 t = __half22float2(*(const __half2*)(g_U0h + (size_t)s * 128 + 64 + c2));
        nx += t.x; ny += t.y;
    }
    float ipv = g_inv_pos[v], inv = g_inv_neg[v];
    float2 sp = *(const float2*)(g_U0s + (size_t)v * 128 + c2);
    float2 sn = *(const float2*)(g_U0s + (size_t)v * 128 + 64 + c2);
    float2 b1 = *(const float2*)(bp + c2);
    float2 b2 = *(const float2*)(bn + c2);
    float zpx = tanhf(ax * ipv + sp.x + b1.x), zpy = tanhf(ay * ipv + sp.y + b1.y);
    float znx = tanhf(nx * inv + sn.x + b2.x), zny = tanhf(ny * inv + sn.y + b2.y);
    *(__half2*)(g_Zh + (size_t)v * 128 + c2) = __floats2half2_rn(zpx, zpy);
    *(__half2*)(g_Zh + (size_t)v * 128 + 64 + c2) = __floats2half2_rn(znx, zny);
}

// ---------------- Layer aggregation: warp-per-node fp16 gather, permuted fp32 output ----------------
__global__ void agg_k(int zsel) {
    const __half* Z = zsel ? g_Z2h : g_Zh;
    int v = (blockIdx.x * blockDim.x + threadIdx.x) >> 5;
    int lane = threadIdx.x & 31;
    if (v >= NN) return;
    int c4 = lane * 4;
    float4 aP = make_float4(0.f, 0.f, 0.f, 0.f);
    float4 aN = make_float4(0.f, 0.f, 0.f, 0.f);
    int b = g_rp_pos[v], e = g_rp_pos[v + 1];
    for (int i = b; i < e; i++) {
        int s = g_src_pos[i];
        uint2 raw = *(const uint2*)(Z + (size_t)s * 128 + c4);
        float2 f0 = __half22float2(*(const __half2*)&raw.x);
        float2 f1 = __half22float2(*(const __half2*)&raw.y);
        aP.x += f0.x; aP.y += f0.y; aP.z += f1.x; aP.w += f1.y;
    }
    b = g_rp_neg[v]; e = g_rp_neg[v + 1];
    for (int i = b; i < e; i++) {
        int s = g_src_neg[i];
        uint2 raw = *(const uint2*)(Z + (size_t)s * 128 + c4);
        float2 f0 = __half22float2(*(const __half2*)&raw.x);
        float2 f1 = __half22float2(*(const __half2*)&raw.y);
        aN.x += f0.x; aN.y += f0.y; aN.z += f1.x; aN.w += f1.y;
    }
    float ipv = g_inv_pos[v], inv = g_inv_neg[v];
    aP.x *= ipv; aP.y *= ipv; aP.z *= ipv; aP.w *= ipv;
    aN.x *= inv; aN.y *= inv; aN.z *= inv; aN.w *= inv;
    if (lane < 16) {
        *(float4*)(g_AGGP + (size_t)v * 128 + c4) = aP;
        *(float4*)(g_AGGN + (size_t)v * 128 + 64 + c4) = aN;
    } else {
        *(float4*)(g_AGGP + (size_t)v * 128 + c4) = aN;
        *(float4*)(g_AGGN + (size_t)v * 128 + c4 - 64) = aP;
    }
}

// ---------------- host launcher ----------------
extern "C" void kernel_launch(void* const* d_in, const int* in_sizes, int n_in,
                              void* d_out, int out_size) {
    const float* x = (const float*)d_in[0];
    const int* pe = (const int*)d_in[1];   // int32 (JAX x64 disabled)
    const int* ne = (const int*)d_in[2];
    const float* Wp_l = (const float*)d_in[3];
    const float* Wp_r = (const float*)d_in[4];
    const float* bp = (const float*)d_in[5];
    const float* Wn_l = (const float*)d_in[6];
    const float* Wn_r = (const float*)d_in[7];
    const float* bn = (const float*)d_in[8];
    const float* Wl_pos = (const float*)d_in[9];
    const float* Wr_pos = (const float*)d_in[10];
    const float* b_pos = (const float*)d_in[11];
    const float* Wl_neg = (const float*)d_in[12];
    const float* Wr_neg = (const float*)d_in[13];
    const float* b_neg = (const float*)d_in[14];
    float* out = (float*)d_out;

    float *dU0s, *dAGGP, *dAGGN;
    __half *dU0h, *dZh, *dZ2h;
    cudaGetSymbolAddress((void**)&dU0h, g_U0h);
    cudaGetSymbolAddress((void**)&dU0s, g_U0s);
    cudaGetSymbolAddress((void**)&dZh, g_Zh);
    cudaGetSymbolAddress((void**)&dZ2h, g_Z2h);
    cudaGetSymbolAddress((void**)&dAGGP, g_AGGP);
    cudaGetSymbolAddress((void**)&dAGGN, g_AGGN);

    // --- weight prep ---
    prep_w_k<<<160, 256>>>(Wl_pos, Wr_pos, Wl_neg, Wr_neg, Wp_l, Wn_l, Wp_r, Wn_r);

    // --- CSR build ---
    zero_cnt_k<<<(2 * NN + 255) / 256, 256>>>();
    hist_k<<<1024, 256>>>(pe + EE, 0);
    hist_k<<<1024, 256>>>(ne + EE, 1);
    const int NB = (NN + 1023) / 1024;
    scan1_k<<<NB, 1024>>>(0);
    scan2_k<<<1, 128>>>(NB);
    scan3_k<<<(NN + 255) / 256, 256>>>(0);
    scatter_k<<<1024, 256>>>(pe, pe + EE, 0);
    scan1_k<<<NB, 1024>>>(1);
    scan2_k<<<1, 128>>>(NB);
    scan3_k<<<(NN + 255) / 256, 256>>>(1);
    scatter_k<<<1024, 256>>>(ne, ne + EE, 1);

    const int NBT = (NN + 127) / 128;  // 782

    // --- layer 0 pre-GEMMs ---
    // colsel 0 (left weights -> gathered, fp16 out), colsel 1 (right weights -> self, fp32 out)
    for (int h = 0; h < 2; h++) {
        mma_gemm_k<<<NBT, 256>>>(x, nullptr, 0, 2, 98304 + 0 * 32768 + h * 8192, 16384,
                                 nullptr, dU0h, h * 64, nullptr, 0, 1);
        mma_gemm_k<<<NBT, 256>>>(x, nullptr, 0, 2, 98304 + 1 * 32768 + h * 8192, 16384,
                                 dU0s, nullptr, h * 64, nullptr, 0, 0);
    }
    const int NBW = (NN * 32 + 255) / 256;
    layer0_k<<<NBW, 256>>>(bp, bn);

    // --- layer 1 ---
    agg_k<<<NBW, 256>>>(0);
    mma_gemm_k<<<NBT, 256>>>(dAGGP, dZh, 0, 3, 0 * 24576, 8192, nullptr, dZ2h, 0, b_pos, 1, 1);
    mma_gemm_k<<<NBT, 256>>>(dAGGN, dZh, 64, 3, 1 * 24576, 8192, nullptr, dZ2h, 64, b_neg, 1, 1);

    // --- layer 2 ---
    agg_k<<<NBW, 256>>>(1);
    mma_gemm_k<<<NBT, 256>>>(dAGGP, dZ2h, 0, 3, 2 * 24576, 8192, out, nullptr, 0, b_pos + 64, 1, 0);
    mma_gemm_k<<<NBT, 256>>>(dAGGN, dZ2h, 64, 3, 3 * 24576, 8192, out, nullptr, 64, b_neg + 64, 1, 0);
}